// round 15
// baseline (speedup 1.0000x reference)
#include <cuda_runtime.h>
#include <cstdint>
#include <cfloat>

// Shapes fixed by the problem: x is (64, 128, 4096) fp32.
#define NPOS   4096
#define NROWS  8192          // 64*128
#define NTILES 33            // tiles of 124 centers (last: 126)
#define NSTRIP 64            // 8192 rows / 128 rows-per-strip
#define NITEMS (NTILES * NSTRIP)   // 2112 work items
#define GRID1  1056          // counts blocks: 2 items each, single wave (<=1184 slots)
#define GRID3  296           // bcast blocks: 148 SMs x 2 resident
#define RMAX   512           // gaussian radius cap (R=28 for width 3)

// Scratch in __device__ globals (no allocations allowed; zero-initialized).
__device__ unsigned int g_counts[NPOS];   // packed totals: peak lo16 | valley hi16
__device__ float        g_vec[NPOS];
__device__ int          g_min_bits;       // nonneg floats: int cmp == float cmp
__device__ int          g_max_bits;

// ---------------------------------------------------------------------------
// K1: counts (proven R11 body), 1056 blocks x 2 work items: one full wave,
// all blocks co-resident, uniform load -> no fractional second wave.
// dd matches the reference exactly: (x[p+1]-x[p]) - (x[p]-x[p-1]).
// ---------------------------------------------------------------------------
__global__ __launch_bounds__(256) void k_counts(const float* __restrict__ x) {
    __shared__ unsigned int scol[128];

    const int tid  = threadIdx.x;
    const int lane = tid & 31;
    const int warp = tid >> 5;                  // 0..7

    // Reset min/max scalars for this graph replay (runs before k_vec).
    if (blockIdx.x == 0 && tid == 0) {
        g_min_bits = 0x7F800000;   // +inf (values are >= 0)
        g_max_bits = 0;
    }

    if (tid < 128) scol[tid] = 0u;
    __syncthreads();

    #pragma unroll
    for (int it = 0; it < 2; it++) {
        const int item  = blockIdx.x + it * GRID1;     // 0..2111
        const int tile  = item % NTILES;
        const int strip = item / NTILES;
        const int s    = tile * 124;                // tile covers x cols [s, s+128)
        const int cmax = (tile == NTILES - 1) ? (NPOS - 2) : (s + 124);
        const int p0   = s + 4 * lane + 1;

        unsigned p0c = 0, p1c = 0, p2c = 0, p3c = 0;   // peak counts
        unsigned v0c = 0, v1c = 0, v2c = 0, v3c = 0;   // valley counts

        const int rowbase = strip * 128 + warp * 16;
        const float* xb = x + (size_t)rowbase * NPOS + s;

        #pragma unroll 4
        for (int k = 0; k < 16; k++) {
            float4 v = __ldcs((const float4*)(xb + (size_t)k * NPOS) + lane);
            // Seam values from the next lane (garbage in lane 31; its
            // dependent centers are masked out at the flush).
            float xn0 = __shfl_down_sync(0xFFFFFFFFu, v.x, 1);
            float xn1 = __shfl_down_sync(0xFFFFFFFFu, v.y, 1);

            float d0 = v.y - v.x;
            float d1 = v.z - v.y;
            float d2 = v.w - v.z;
            float d3 = xn0 - v.w;
            float d4 = xn1 - xn0;

            float dd0 = d1 - d0;   // center p0
            float dd1 = d2 - d1;   // center p0+1
            float dd2 = d3 - d2;   // center p0+2
            float dd3 = d4 - d3;   // center p0+3

            p0c += (dd0 < 0.0f); v0c += (dd0 > 0.0f);
            p1c += (dd1 < 0.0f); v1c += (dd1 > 0.0f);
            p2c += (dd2 < 0.0f); v2c += (dd2 > 0.0f);
            p3c += (dd3 < 0.0f); v3c += (dd3 > 0.0f);
        }

        const int i0 = 4 * lane;
        if (p0 + 0 <= cmax) atomicAdd(&scol[i0 + 0], p0c | (v0c << 16));
        if (p0 + 1 <= cmax) atomicAdd(&scol[i0 + 1], p1c | (v1c << 16));
        if (p0 + 2 <= cmax) atomicAdd(&scol[i0 + 2], p2c | (v2c << 16));
        if (p0 + 3 <= cmax) atomicAdd(&scol[i0 + 3], p3c | (v3c << 16));
        __syncthreads();

        const int ncols = cmax - s;             // 124 (126 for last tile)
        if (tid < ncols) {
            atomicAdd(&g_counts[s + 1 + tid], scol[tid]);
        }
        if (tid < 128) scol[tid] = 0u;          // owner-reset for next item
        __syncthreads();
    }
}

// ---------------------------------------------------------------------------
// K2: 32 blocks x 128 threads. Reads 16KB of L2-hot totals, gaussian conv,
// block-reduced atomic min/max. Tail beyond R = 9w+1 < exp(-81): fp32 zero.
// (unchanged from R11)
// ---------------------------------------------------------------------------
__global__ __launch_bounds__(128) void k_vec(const float* __restrict__ lpw,
                                             const float* __restrict__ lvw) {
    __shared__ unsigned int scnt[128 + 2 * RMAX];
    __shared__ float sgp[RMAX + 1];
    __shared__ float sgv[RMAX + 1];
    __shared__ float smn[4], smx[4];

    const int t = threadIdx.x;

    const float wp = expf(*lpw);
    const float wv = expf(*lvw);
    int R = (int)(9.0f * fmaxf(wp, wv)) + 1;
    if (R > RMAX) R = RMAX;

    for (int d = t; d <= R; d += 128) {
        float fd = (float)d;
        float tp = fd / wp;
        float tv = fd / wv;
        sgp[d] = expf(-tp * tp);
        sgv[d] = expf(-tv * tv);
    }

    const int pbase = blockIdx.x * 128;      // outputs [pbase, pbase+128)
    const int sbase = pbase - R;
    const int span  = 128 + 2 * R;
    for (int j = t; j < span; j += 128) {
        const int c = sbase + j;
        scnt[j] = ((unsigned)(c - 1) <= (unsigned)(NPOS - 3)) ? g_counts[c] : 0u;
    }
    __syncthreads();

    // Symmetric-pair convolution: packed u16 fields hold sums <= 16384, safe.
    const int ci = t + R;
    unsigned pk0 = scnt[ci];
    float acc = (float)(pk0 & 0xFFFFu) * sgp[0] + (float)(pk0 >> 16) * sgv[0];
    for (int d = 1; d <= R; d++) {
        unsigned pk = scnt[ci + d] + scnt[ci - d];
        acc += (float)(pk & 0xFFFFu) * sgp[d] + (float)(pk >> 16) * sgv[d];
    }
    g_vec[pbase + t] = acc;

    float mn = acc, mx = acc;
    #pragma unroll
    for (int o = 16; o > 0; o >>= 1) {
        mn = fminf(mn, __shfl_xor_sync(0xFFFFFFFFu, mn, o));
        mx = fmaxf(mx, __shfl_xor_sync(0xFFFFFFFFu, mx, o));
    }
    if ((t & 31) == 0) { smn[t >> 5] = mn; smx[t >> 5] = mx; }
    __syncthreads();
    if (t == 0) {
        mn = fminf(fminf(smn[0], smn[1]), fminf(smn[2], smn[3]));
        mx = fmaxf(fmaxf(smx[0], smx[1]), fmaxf(smx[2], smx[3]));
        atomicMin(&g_min_bits, __float_as_int(mn));  // nonneg floats
        atomicMax(&g_max_bits, __float_as_int(mx));
    }
}

// ---------------------------------------------------------------------------
// K3: normalize + broadcast. 296 blocks (one full wave), strided row loop:
// 27-28 rows per block (3.7% imbalance) instead of a 73%-full second wave.
// Plain float4 stores (proven fastest). Block 0 zeroes g_counts for the
// next replay (ordered after k_vec consumed it).
// ---------------------------------------------------------------------------
__global__ __launch_bounds__(1024) void k_bcast(float* __restrict__ out) {
    const int t = threadIdx.x;

    if (blockIdx.x == 0) {
        #pragma unroll
        for (int q = 0; q < 4; q++) g_counts[t + q * 1024] = 0u;
    }

    const float mn = __int_as_float(g_min_bits);
    const float inv = 1.0f / (__int_as_float(g_max_bits) - mn + 1e-6f);

    float4 v = ((const float4*)g_vec)[t];
    v.x = (v.x - mn) * inv;
    v.y = (v.y - mn) * inv;
    v.z = (v.z - mn) * inv;
    v.w = (v.w - mn) * inv;

    float4* ob = (float4*)out + t;
    for (int row = blockIdx.x; row < NROWS; row += GRID3) {
        ob[(size_t)row * 1024] = v;
    }
}

// ---------------------------------------------------------------------------
extern "C" void kernel_launch(void* const* d_in, const int* in_sizes, int n_in,
                              void* d_out, int out_size) {
    const float* x   = (const float*)d_in[0];
    const float* lpw = (const float*)d_in[1];
    const float* lvw = (const float*)d_in[2];
    float* out = (float*)d_out;

    k_counts<<<GRID1, 256>>>(x);
    k_vec<<<NPOS / 128, 128>>>(lpw, lvw);
    k_bcast<<<GRID3, 1024>>>(out);
}

// round 16
// speedup vs baseline: 1.1491x; 1.1491x over previous
#include <cuda_runtime.h>
#include <cstdint>
#include <cfloat>

// Shapes fixed by the problem: x is (64, 128, 4096) fp32.
#define NPOS   4096
#define NROWS  8192          // 64*128
#define NTILES 33            // tiles of 124 centers (last: 126)
#define NSTRIP 128           // 8192 rows / 64 rows-per-strip (8 rows per warp)
#define RMAX   512           // gaussian radius cap (R=28 for width 3)

// Scratch in __device__ globals (no allocations allowed; zero-initialized).
__device__ unsigned int g_counts[NPOS];   // packed totals: peak lo16 | valley hi16
__device__ float        g_vec[NPOS];
__device__ int          g_min_bits;       // nonneg floats: int cmp == float cmp
__device__ int          g_max_bits;

// ---------------------------------------------------------------------------
// K1: counts (proven R11 inner body). Finer granularity: 4224 blocks, each
// warp does 8 rows — more concurrent blocks = more outstanding loads for
// the latency-bound read path. Direct atomic flush into totals.
// dd matches the reference exactly: (x[p+1]-x[p]) - (x[p]-x[p-1]).
// ---------------------------------------------------------------------------
__global__ __launch_bounds__(256) void k_counts(const float* __restrict__ x) {
    __shared__ unsigned int scol[128];

    const int tid  = threadIdx.x;
    const int lane = tid & 31;
    const int warp = tid >> 5;                  // 0..7
    const int tile = blockIdx.x;                // 0..32
    const int s    = tile * 124;                // tile covers x columns [s, s+128)
    const int cmax = (tile == NTILES - 1) ? (NPOS - 2) : (s + 124);
    const int p0   = s + 4 * lane + 1;

    // Reset min/max scalars for this graph replay (runs before k_vec).
    if (tile == 0 && blockIdx.y == 0 && tid == 0) {
        g_min_bits = 0x7F800000;   // +inf (values are >= 0)
        g_max_bits = 0;
    }

    if (tid < 128) scol[tid] = 0u;
    __syncthreads();

    unsigned p0c = 0, p1c = 0, p2c = 0, p3c = 0;   // peak counts
    unsigned v0c = 0, v1c = 0, v2c = 0, v3c = 0;   // valley counts

    const int rowbase = blockIdx.y * 64 + warp * 8;
    const float* xb = x + (size_t)rowbase * NPOS + s;

    #pragma unroll 4
    for (int k = 0; k < 8; k++) {
        float4 v = __ldcs((const float4*)(xb + (size_t)k * NPOS) + lane);
        // Seam values from the next lane (garbage in lane 31; its dependent
        // centers are masked out at the flush).
        float xn0 = __shfl_down_sync(0xFFFFFFFFu, v.x, 1);
        float xn1 = __shfl_down_sync(0xFFFFFFFFu, v.y, 1);

        float d0 = v.y - v.x;
        float d1 = v.z - v.y;
        float d2 = v.w - v.z;
        float d3 = xn0 - v.w;
        float d4 = xn1 - xn0;

        float dd0 = d1 - d0;   // center p0
        float dd1 = d2 - d1;   // center p0+1
        float dd2 = d3 - d2;   // center p0+2
        float dd3 = d4 - d3;   // center p0+3

        p0c += (dd0 < 0.0f); v0c += (dd0 > 0.0f);
        p1c += (dd1 < 0.0f); v1c += (dd1 > 0.0f);
        p2c += (dd2 < 0.0f); v2c += (dd2 > 0.0f);
        p3c += (dd3 < 0.0f); v3c += (dd3 > 0.0f);
    }

    const int i0 = 4 * lane;
    if (p0 + 0 <= cmax) atomicAdd(&scol[i0 + 0], p0c | (v0c << 16));
    if (p0 + 1 <= cmax) atomicAdd(&scol[i0 + 1], p1c | (v1c << 16));
    if (p0 + 2 <= cmax) atomicAdd(&scol[i0 + 2], p2c | (v2c << 16));
    if (p0 + 3 <= cmax) atomicAdd(&scol[i0 + 3], p3c | (v3c << 16));
    __syncthreads();

    const int ncols = cmax - s;                 // 124 (126 for last tile)
    if (tid < ncols) {
        atomicAdd(&g_counts[s + 1 + tid], scol[tid]);
    }
}

// ---------------------------------------------------------------------------
// K2: 32 blocks x 128 threads. Reads 16KB of L2-hot totals, gaussian conv,
// block-reduced atomic min/max. Tail beyond R = 9w+1 < exp(-81): fp32 zero.
// (unchanged from R11)
// ---------------------------------------------------------------------------
__global__ __launch_bounds__(128) void k_vec(const float* __restrict__ lpw,
                                             const float* __restrict__ lvw) {
    __shared__ unsigned int scnt[128 + 2 * RMAX];
    __shared__ float sgp[RMAX + 1];
    __shared__ float sgv[RMAX + 1];
    __shared__ float smn[4], smx[4];

    const int t = threadIdx.x;

    const float wp = expf(*lpw);
    const float wv = expf(*lvw);
    int R = (int)(9.0f * fmaxf(wp, wv)) + 1;
    if (R > RMAX) R = RMAX;

    for (int d = t; d <= R; d += 128) {
        float fd = (float)d;
        float tp = fd / wp;
        float tv = fd / wv;
        sgp[d] = expf(-tp * tp);
        sgv[d] = expf(-tv * tv);
    }

    const int pbase = blockIdx.x * 128;      // outputs [pbase, pbase+128)
    const int sbase = pbase - R;
    const int span  = 128 + 2 * R;
    for (int j = t; j < span; j += 128) {
        const int c = sbase + j;
        scnt[j] = ((unsigned)(c - 1) <= (unsigned)(NPOS - 3)) ? g_counts[c] : 0u;
    }
    __syncthreads();

    // Symmetric-pair convolution: packed u16 fields hold sums <= 16384, safe.
    const int ci = t + R;
    unsigned pk0 = scnt[ci];
    float acc = (float)(pk0 & 0xFFFFu) * sgp[0] + (float)(pk0 >> 16) * sgv[0];
    for (int d = 1; d <= R; d++) {
        unsigned pk = scnt[ci + d] + scnt[ci - d];
        acc += (float)(pk & 0xFFFFu) * sgp[d] + (float)(pk >> 16) * sgv[d];
    }
    g_vec[pbase + t] = acc;

    float mn = acc, mx = acc;
    #pragma unroll
    for (int o = 16; o > 0; o >>= 1) {
        mn = fminf(mn, __shfl_xor_sync(0xFFFFFFFFu, mn, o));
        mx = fmaxf(mx, __shfl_xor_sync(0xFFFFFFFFu, mx, o));
    }
    if ((t & 31) == 0) { smn[t >> 5] = mn; smx[t >> 5] = mx; }
    __syncthreads();
    if (t == 0) {
        mn = fminf(fminf(smn[0], smn[1]), fminf(smn[2], smn[3]));
        mx = fmaxf(fmaxf(smx[0], smx[1]), fmaxf(smx[2], smx[3]));
        atomicMin(&g_min_bits, __float_as_int(mn));  // nonneg floats
        atomicMax(&g_max_bits, __float_as_int(mx));
    }
}

// ---------------------------------------------------------------------------
// K3: normalize + broadcast. Finer granularity: 1024 blocks x 8 rows (the
// kernel is latency-bound: issue 4.5%, DRAM 43% — deeper block concurrency).
// Plain float4 stores (proven fastest). Block 0 zeroes g_counts for the
// next replay (ordered after k_vec consumed it).
// ---------------------------------------------------------------------------
__global__ __launch_bounds__(1024) void k_bcast(float* __restrict__ out) {
    const int t = threadIdx.x;

    if (blockIdx.x == 0) {
        #pragma unroll
        for (int q = 0; q < 4; q++) g_counts[t + q * 1024] = 0u;
    }

    const float mn = __int_as_float(g_min_bits);
    const float inv = 1.0f / (__int_as_float(g_max_bits) - mn + 1e-6f);

    float4 v = ((const float4*)g_vec)[t];
    v.x = (v.x - mn) * inv;
    v.y = (v.y - mn) * inv;
    v.z = (v.z - mn) * inv;
    v.w = (v.w - mn) * inv;

    float4* o = (float4*)out + (size_t)blockIdx.x * 8 * 1024 + t;
    #pragma unroll
    for (int r = 0; r < 8; r++) {
        o[(size_t)r * 1024] = v;
    }
}

// ---------------------------------------------------------------------------
extern "C" void kernel_launch(void* const* d_in, const int* in_sizes, int n_in,
                              void* d_out, int out_size) {
    const float* x   = (const float*)d_in[0];
    const float* lpw = (const float*)d_in[1];
    const float* lvw = (const float*)d_in[2];
    float* out = (float*)d_out;

    k_counts<<<dim3(NTILES, NSTRIP), 256>>>(x);
    k_vec<<<NPOS / 128, 128>>>(lpw, lvw);
    k_bcast<<<NROWS / 8, 1024>>>(out);
}